// round 1
// baseline (speedup 1.0000x reference)
#include <cuda_runtime.h>
#include <math.h>

// Problem constants (fixed by setup_inputs)
#define NPIX 32768      // B*H*W = 8*64*64
#define PP   4096       // H*W
#define CC   2048       // channels (GEMM K)
#define DD   256        // projection dim (GEMM N)
#define NMEM 256        // memory bank rows
#define NS   64         // NUM_SAMPLES
#define NA   16         // anchors per class (NUM_ANCHORS/2)

typedef unsigned long long ull;

// ---------------- device scratch (static: no allocations allowed) ----------
__device__ float g_z[(size_t)NPIX * DD];        // projected features (pre-BN)  ~33.5MB
__device__ float g_psum[256 * DD];              // per-block column sums
__device__ float g_psq[256 * DD];               // per-block column sums of squares
__device__ int   g_sel_idx[128];                // fg[0..63], bg[64..127]
__device__ float g_sel_valid[128];
__device__ float g_nf[128 * DD];                // normalized selected features

// =====================================================================
// Kernel 1: hard-sample mining. block 0 -> fg (label==1), block 1 -> bg.
// Iterative block-argmax (64 rounds) replicating jax.lax.top_k exactly,
// including lower-index-first tie-breaking.
// =====================================================================
__global__ void k_select(const float* __restrict__ pred_ori,
                         const float* __restrict__ pred_aug,
                         const float* __restrict__ unc,
                         const int*   __restrict__ labels)
{
    const int cls = blockIdx.x;          // 0: fg, 1: bg
    const int tid = threadIdx.x;         // 1024 threads
    const int want = cls ? 0 : 1;

    float sc[32];
    #pragma unroll
    for (int i = 0; i < 32; i++) {
        int n = tid + (i << 10);
        int b = n >> 12, p = n & 4095;
        const float* po = pred_ori + (size_t)b * 2 * PP + p;
        const float* pa = pred_aug + (size_t)b * 2 * PP + p;
        int io = po[PP] > po[0];         // argmax over 2 classes (tie -> 0)
        int ia = pa[PP] > pa[0];
        float u = unc[n];
        bool ok = (io == ia) && (u > 0.5f) && (labels[n] == want);
        sc[i] = ok ? u : -1e9f;
    }

    // cached per-thread argmax
    float bv = -INFINITY; int bi = -1;
    #pragma unroll
    for (int i = 0; i < 32; i++) {
        int n = tid + (i << 10);
        if (sc[i] > bv || (sc[i] == bv && n < bi)) { bv = sc[i]; bi = n; }
    }

    __shared__ float wv[32];
    __shared__ int   wi[32];
    __shared__ int   winner;

    for (int it = 0; it < NS; it++) {
        float v = bv; int ix = bi;
        #pragma unroll
        for (int o = 16; o; o >>= 1) {
            float ov = __shfl_down_sync(0xffffffffu, v, o);
            int   oi = __shfl_down_sync(0xffffffffu, ix, o);
            if (ov > v || (ov == v && oi < ix)) { v = ov; ix = oi; }
        }
        if ((tid & 31) == 0) { wv[tid >> 5] = v; wi[tid >> 5] = ix; }
        __syncthreads();
        if (tid < 32) {
            v = wv[tid]; ix = wi[tid];
            #pragma unroll
            for (int o = 16; o; o >>= 1) {
                float ov = __shfl_down_sync(0xffffffffu, v, o);
                int   oi = __shfl_down_sync(0xffffffffu, ix, o);
                if (ov > v || (ov == v && oi < ix)) { v = ov; ix = oi; }
            }
            if (tid == 0) {
                winner = ix;
                g_sel_idx[cls * NS + it]   = ix;
                g_sel_valid[cls * NS + it] = (v > -5e8f) ? 1.0f : 0.0f;
            }
        }
        __syncthreads();
        int wn = winner;
        if ((wn & 1023) == tid) {
            sc[wn >> 10] = -INFINITY;
            bv = -INFINITY; bi = -1;
            #pragma unroll
            for (int i = 0; i < 32; i++) {
                int n = tid + (i << 10);
                if (sc[i] > bv || (sc[i] == bv && n < bi)) { bv = sc[i]; bi = n; }
            }
        }
        __syncthreads();
    }
}

// =====================================================================
// Kernel 2: projection GEMM.  Z[n,d] = sum_c F[n,c] * W[c,d]
// A is stored K-major per batch (features layout [B,C,H*W]), so A tiles
// load contiguously along pixels. 128x128x8 tiling, 8x8 microtile/thread,
// accumulators as packed f32x2 (fma.rn.f32x2 = 2 FMA per issue).
// conv_b omitted: it cancels exactly in BatchNorm.
// =====================================================================
__device__ __forceinline__ void ffma2(ull& c, ull a, ull b) {
    asm("fma.rn.f32x2 %0, %1, %2, %0;" : "+l"(c) : "l"(a), "l"(b));
}
__device__ __forceinline__ ull bcast2(float x) {
    ull r;
    asm("mov.b64 %0, {%1, %1};" : "=l"(r) : "r"(__float_as_uint(x)));
    return r;
}

__global__ void __launch_bounds__(256) k_gemm(const float* __restrict__ F,
                                              const float* __restrict__ Wm)
{
    __shared__ float As[8][128];
    __shared__ float Bs[8][128];

    const int tid = threadIdx.x;
    const int m0 = blockIdx.y * 128;   // pixel tile (never crosses batch: 4096%128==0)
    const int n0 = blockIdx.x * 128;   // output-dim tile
    const int b  = m0 >> 12;

    const float* Ab = F + (size_t)b * CC * PP + (m0 & 4095); // A(k,j) = Ab[k*PP + j]
    const float* Bb = Wm + n0;                               // B(k,j) = Bb[k*DD + j]

    const int lk = tid >> 5;           // 0..7  (k row for loads)
    const int lm = (tid & 31) << 2;    // 0..124 (vec4 col for loads)

    const int tx = tid & 15, ty = tid >> 4;
    const int crow = ty * 8, ccol = tx * 8;

    ull acc[4][8];
    #pragma unroll
    for (int i = 0; i < 4; i++)
        #pragma unroll
        for (int j = 0; j < 8; j++) acc[i][j] = 0ull;

    float4 a4 = *(const float4*)(Ab + (size_t)lk * PP + lm);
    float4 b4 = *(const float4*)(Bb + lk * DD + lm);
    *(float4*)&As[lk][lm] = a4;
    *(float4*)&Bs[lk][lm] = b4;
    __syncthreads();

    const int KT = CC / 8;   // 256 k-tiles
    for (int kt = 0; kt < KT; kt++) {
        float4 a4n, b4n;
        if (kt + 1 < KT) {
            a4n = *(const float4*)(Ab + (size_t)((kt + 1) * 8 + lk) * PP + lm);
            b4n = *(const float4*)(Bb + ((kt + 1) * 8 + lk) * DD + lm);
        }
        #pragma unroll
        for (int k = 0; k < 8; k++) {
            const ull* arow = (const ull*)&As[k][crow];   // 4 row-pairs, LDS.64-native
            ull ap0 = arow[0], ap1 = arow[1], ap2 = arow[2], ap3 = arow[3];
            float4 bq0 = *(const float4*)&Bs[k][ccol];
            float4 bq1 = *(const float4*)&Bs[k][ccol + 4];
            float bs[8] = {bq0.x, bq0.y, bq0.z, bq0.w, bq1.x, bq1.y, bq1.z, bq1.w};
            #pragma unroll
            for (int j = 0; j < 8; j++) {
                ull bb = bcast2(bs[j]);
                ffma2(acc[0][j], ap0, bb);
                ffma2(acc[1][j], ap1, bb);
                ffma2(acc[2][j], ap2, bb);
                ffma2(acc[3][j], ap3, bb);
            }
        }
        __syncthreads();
        if (kt + 1 < KT) {
            *(float4*)&As[lk][lm] = a4n;
            *(float4*)&Bs[lk][lm] = b4n;
            __syncthreads();
        }
    }

    // epilogue: unpack row-pairs, vectorized store
    #pragma unroll
    for (int ip = 0; ip < 4; ip++) {
        float lo[8], hi[8];
        #pragma unroll
        for (int j = 0; j < 8; j++) {
            lo[j] = __uint_as_float((unsigned)(acc[ip][j] & 0xffffffffull));
            hi[j] = __uint_as_float((unsigned)(acc[ip][j] >> 32));
        }
        int r0 = m0 + crow + 2 * ip;
        float* z0 = g_z + (size_t)r0 * DD + n0 + ccol;
        float* z1 = z0 + DD;
        ((float4*)z0)[0] = make_float4(lo[0], lo[1], lo[2], lo[3]);
        ((float4*)z0)[1] = make_float4(lo[4], lo[5], lo[6], lo[7]);
        ((float4*)z1)[0] = make_float4(hi[0], hi[1], hi[2], hi[3]);
        ((float4*)z1)[1] = make_float4(hi[4], hi[5], hi[6], hi[7]);
    }
}

// =====================================================================
// Kernel 3: per-column partial sums/sumsq over 128-row slabs of g_z
// =====================================================================
__global__ void k_colred()
{
    const int blk = blockIdx.x;   // 256 blocks
    const int t   = threadIdx.x;  // 256 threads (one column each)
    const float* base = g_z + (size_t)blk * 128 * DD + t;
    float s = 0.f, q = 0.f;
    #pragma unroll 4
    for (int r = 0; r < 128; r++) {
        float v = base[(size_t)r * DD];
        s += v;
        q += v * v;
    }
    g_psum[blk * DD + t] = s;
    g_psq [blk * DD + t] = q;
}

// =====================================================================
// Kernel 4: finalize (single block).
//   A) BN stats from partials
//   B) gather+BN+ReLU+L2-normalize the 128 selected rows -> g_nf
//   B2) memory-bank inverse norms
//   C) 4x InfoNCE (64 warp-tasks), scalar output
// =====================================================================
__global__ void k_final(const float* __restrict__ gamma,
                        const float* __restrict__ beta,
                        const float* __restrict__ mpos,
                        const float* __restrict__ mneg,
                        float* __restrict__ out)
{
    __shared__ float s_mu[DD], s_istd[DD];
    __shared__ float s_mn[2 * NMEM];     // inverse norms: [0..255]=mpos, [256..511]=mneg
    __shared__ float s_acc[2];           // local / global loss sums
    __shared__ float s_cnt;

    const int t = threadIdx.x;           // 256 threads
    const int warp = t >> 5, lane = t & 31;
    if (t == 0) { s_acc[0] = 0.f; s_acc[1] = 0.f; s_cnt = 0.f; }

    // ---- A: BN statistics ----
    {
        float s = 0.f, q = 0.f;
        for (int b = 0; b < 256; b++) { s += g_psum[b * DD + t]; q += g_psq[b * DD + t]; }
        float mu  = s * (1.0f / 32768.0f);
        float var = q * (1.0f / 32768.0f) - mu * mu;
        s_mu[t]   = mu;
        s_istd[t] = 1.0f / sqrtf(var + 1e-5f);
    }
    __syncthreads();

    // ---- B: project + normalize selected rows ----
    for (int s = warp; s < 128; s += 8) {
        int row = g_sel_idx[s];
        const float* zr = g_z + (size_t)row * DD;
        float v[8]; float ss = 0.f;
        #pragma unroll
        for (int k = 0; k < 8; k++) {
            int d = lane + 32 * k;
            float x = (zr[d] - s_mu[d]) * s_istd[d] * gamma[d] + beta[d];
            x = fmaxf(x, 0.f);
            v[k] = x; ss += x * x;
        }
        #pragma unroll
        for (int o = 16; o; o >>= 1) ss += __shfl_xor_sync(0xffffffffu, ss, o);
        float inv = 1.0f / (sqrtf(ss) + 1e-12f);
        #pragma unroll
        for (int k = 0; k < 8; k++) g_nf[s * DD + lane + 32 * k] = v[k] * inv;
    }

    // ---- B2: memory inverse norms ----
    for (int r = warp; r < 2 * NMEM; r += 8) {
        const float* m = (r < NMEM) ? (mpos + (size_t)r * DD)
                                    : (mneg + (size_t)(r - NMEM) * DD);
        float ss = 0.f;
        #pragma unroll
        for (int k = 0; k < 8; k++) { float x = m[lane + 32 * k]; ss += x * x; }
        #pragma unroll
        for (int o = 16; o; o >>= 1) ss += __shfl_xor_sync(0xffffffffu, ss, o);
        if (lane == 0) s_mn[r] = 1.0f / (sqrtf(ss) + 1e-12f);
    }
    __syncthreads();   // g_nf (global, same block) + s_mn visible

    // ---- C: InfoNCE tasks. task = loss*16 + anchor; loss: 0=l1 1=l2 2=g1 3=g2
    for (int task = warp; task < 64; task += 8) {
        int loss = task >> 4;
        int a    = task & 15;
        int qslot = (loss == 1 || loss == 3) ? (NS + a) : a;
        const float* qv = g_nf + (size_t)qslot * DD;
        float qvalid = g_sel_valid[qslot];
        float pe = 0.f, ne = 0.f;

        if (loss < 2) {
            int posbase = (loss == 0) ? 0 : NS;
            int negbase = NS - posbase;
            for (int j = 0; j < NS; j++) {
                const float* p = g_nf + (size_t)(posbase + j) * DD;
                float d = 0.f;
                #pragma unroll
                for (int k = 0; k < 8; k++) d += qv[lane + 32 * k] * p[lane + 32 * k];
                #pragma unroll
                for (int o = 16; o; o >>= 1) d += __shfl_xor_sync(0xffffffffu, d, o);
                pe += expf(d * 10.0f) * g_sel_valid[posbase + j];

                const float* n2 = g_nf + (size_t)(negbase + j) * DD;
                float dn = 0.f;
                #pragma unroll
                for (int k = 0; k < 8; k++) dn += qv[lane + 32 * k] * n2[lane + 32 * k];
                #pragma unroll
                for (int o = 16; o; o >>= 1) dn += __shfl_xor_sync(0xffffffffu, dn, o);
                ne += expf(dn * 10.0f) * g_sel_valid[negbase + j];
            }
        } else {
            const float* pb = (loss == 2) ? mpos : mneg;
            const float* nb = (loss == 2) ? mneg : mpos;
            int pno = (loss == 2) ? 0 : NMEM;       // s_mn offset of the pos bank
            for (int j = 0; j < NMEM; j++) {
                const float* p = pb + (size_t)j * DD;
                float d = 0.f;
                #pragma unroll
                for (int k = 0; k < 8; k++) d += qv[lane + 32 * k] * p[lane + 32 * k];
                #pragma unroll
                for (int o = 16; o; o >>= 1) d += __shfl_xor_sync(0xffffffffu, d, o);
                pe += expf(d * s_mn[pno + j] * 10.0f);

                const float* n2 = nb + (size_t)j * DD;
                float dn = 0.f;
                #pragma unroll
                for (int k = 0; k < 8; k++) dn += qv[lane + 32 * k] * n2[lane + 32 * k];
                #pragma unroll
                for (int o = 16; o; o >>= 1) dn += __shfl_xor_sync(0xffffffffu, dn, o);
                ne += expf(dn * s_mn[(pno ^ NMEM) + j] * 10.0f);
            }
        }
        if (lane == 0) {
            float lv = -logf(pe / (pe + ne + 1e-8f) + 1e-8f);
            atomicAdd(&s_acc[loss >> 1], lv * qvalid);
            if (loss < 2) atomicAdd(&s_cnt, qvalid);
        }
    }
    __syncthreads();
    if (t == 0) {
        float n = fmaxf(s_cnt, 1.0f);
        out[0] = s_acc[0] / n + s_acc[1] / n;
    }
}

// =====================================================================
extern "C" void kernel_launch(void* const* d_in, const int* in_sizes, int n_in,
                              void* d_out, int out_size)
{
    const float* features = (const float*)d_in[0];
    const float* pred_ori = (const float*)d_in[1];
    const float* pred_aug = (const float*)d_in[2];
    const float* unc      = (const float*)d_in[3];
    const int*   labels   = (const int*)  d_in[4];
    const float* conv_w   = (const float*)d_in[5];
    // d_in[6] = conv_b: cancels exactly in BatchNorm -> unused
    const float* gamma    = (const float*)d_in[7];
    const float* beta     = (const float*)d_in[8];
    const float* mpos     = (const float*)d_in[9];
    const float* mneg     = (const float*)d_in[10];

    k_select<<<2, 1024>>>(pred_ori, pred_aug, unc, labels);
    dim3 ggrid(DD / 128, NPIX / 128);   // (2, 256)
    k_gemm<<<ggrid, 256>>>(features, conv_w);
    k_colred<<<256, 256>>>();
    k_final<<<1, 256>>>(gamma, beta, mpos, mneg, (float*)d_out);
}

// round 2
// speedup vs baseline: 1.6479x; 1.6479x over previous
#include <cuda_runtime.h>
#include <math.h>

// Problem constants (fixed by setup_inputs)
#define NPIX 32768      // B*H*W = 8*64*64
#define PP   4096       // H*W
#define CC   2048       // channels (GEMM K)
#define DD   256        // projection dim (GEMM N)
#define NMEM 256        // memory bank rows
#define NS   64         // NUM_SAMPLES
#define NA   16         // anchors per class (NUM_ANCHORS/2)

typedef unsigned long long ull;

// ---------------- device scratch (static: no allocations allowed) ----------
__device__ float g_z[(size_t)NPIX * DD];        // projected features (pre-BN)  ~33.5MB
__device__ float g_psum[256 * DD];              // per-m-tile column sums   (written by GEMM epilogue)
__device__ float g_psq[256 * DD];               // per-m-tile column sumsq
__device__ int   g_sel_idx[128];                // fg[0..63], bg[64..127]
__device__ float g_sel_valid[128];
__device__ float g_nf[128 * DD];                // normalized selected features
__device__ float g_mn[2 * NMEM];                // memory-bank inverse norms
__device__ float g_acc[2];                      // local / global loss sums
__device__ float g_cnt;

// =====================================================================
// Kernel 1: hard-sample mining. block 0 -> fg (label==1), block 1 -> bg.
// Iterative block-argmax (64 rounds) replicating jax.lax.top_k exactly,
// including lower-index-first tie-breaking.
// =====================================================================
__global__ void k_select(const float* __restrict__ pred_ori,
                         const float* __restrict__ pred_aug,
                         const float* __restrict__ unc,
                         const int*   __restrict__ labels)
{
    const int cls = blockIdx.x;          // 0: fg, 1: bg
    const int tid = threadIdx.x;         // 1024 threads
    const int want = cls ? 0 : 1;

    float sc[32];
    #pragma unroll
    for (int i = 0; i < 32; i++) {
        int n = tid + (i << 10);
        int b = n >> 12, p = n & 4095;
        const float* po = pred_ori + (size_t)b * 2 * PP + p;
        const float* pa = pred_aug + (size_t)b * 2 * PP + p;
        int io = po[PP] > po[0];         // argmax over 2 classes (tie -> 0)
        int ia = pa[PP] > pa[0];
        float u = unc[n];
        bool ok = (io == ia) && (u > 0.5f) && (labels[n] == want);
        sc[i] = ok ? u : -1e9f;
    }

    // cached per-thread argmax
    float bv = -INFINITY; int bi = -1;
    #pragma unroll
    for (int i = 0; i < 32; i++) {
        int n = tid + (i << 10);
        if (sc[i] > bv || (sc[i] == bv && n < bi)) { bv = sc[i]; bi = n; }
    }

    __shared__ float wv[32];
    __shared__ int   wi[32];
    __shared__ int   winner;

    for (int it = 0; it < NS; it++) {
        float v = bv; int ix = bi;
        #pragma unroll
        for (int o = 16; o; o >>= 1) {
            float ov = __shfl_down_sync(0xffffffffu, v, o);
            int   oi = __shfl_down_sync(0xffffffffu, ix, o);
            if (ov > v || (ov == v && oi < ix)) { v = ov; ix = oi; }
        }
        if ((tid & 31) == 0) { wv[tid >> 5] = v; wi[tid >> 5] = ix; }
        __syncthreads();
        if (tid < 32) {
            v = wv[tid]; ix = wi[tid];
            #pragma unroll
            for (int o = 16; o; o >>= 1) {
                float ov = __shfl_down_sync(0xffffffffu, v, o);
                int   oi = __shfl_down_sync(0xffffffffu, ix, o);
                if (ov > v || (ov == v && oi < ix)) { v = ov; ix = oi; }
            }
            if (tid == 0) {
                winner = ix;
                g_sel_idx[cls * NS + it]   = ix;
                g_sel_valid[cls * NS + it] = (v > -5e8f) ? 1.0f : 0.0f;
            }
        }
        __syncthreads();
        int wn = winner;
        if ((wn & 1023) == tid) {
            sc[wn >> 10] = -INFINITY;
            bv = -INFINITY; bi = -1;
            #pragma unroll
            for (int i = 0; i < 32; i++) {
                int n = tid + (i << 10);
                if (sc[i] > bv || (sc[i] == bv && n < bi)) { bv = sc[i]; bi = n; }
            }
        }
        __syncthreads();
    }
}

// =====================================================================
// Kernel 2: projection GEMM.  Z[n,d] = sum_c F[n,c] * W[c,d]
// 128x128x8 tiling, 8x8 microtile/thread, accumulators as packed f32x2
// (fma.rn.f32x2 = 2 FMA per issue). conv_b omitted: cancels in BatchNorm.
// Epilogue additionally reduces per-tile column sums / sumsq into
// g_psum/g_psq (each (m-tile, col) written exactly once -> no atomics).
// =====================================================================
__device__ __forceinline__ void ffma2(ull& c, ull a, ull b) {
    asm("fma.rn.f32x2 %0, %1, %2, %0;" : "+l"(c) : "l"(a), "l"(b));
}
__device__ __forceinline__ ull bcast2(float x) {
    ull r;
    asm("mov.b64 %0, {%1, %1};" : "=l"(r) : "r"(__float_as_uint(x)));
    return r;
}

__global__ void __launch_bounds__(256) k_gemm(const float* __restrict__ F,
                                              const float* __restrict__ Wm)
{
    __shared__ float As[8][128];
    __shared__ float Bs[8][128];
    __shared__ float red[16][128];     // column-sum reduction scratch

    const int tid = threadIdx.x;
    const int m0 = blockIdx.y * 128;   // pixel tile (never crosses batch: 4096%128==0)
    const int n0 = blockIdx.x * 128;   // output-dim tile
    const int by = blockIdx.y;
    const int b  = m0 >> 12;

    const float* Ab = F + (size_t)b * CC * PP + (m0 & 4095); // A(k,j) = Ab[k*PP + j]
    const float* Bb = Wm + n0;                               // B(k,j) = Bb[k*DD + j]

    const int lk = tid >> 5;           // 0..7  (k row for loads)
    const int lm = (tid & 31) << 2;    // 0..124 (vec4 col for loads)

    const int tx = tid & 15, ty = tid >> 4;
    const int crow = ty * 8, ccol = tx * 8;

    ull acc[4][8];
    #pragma unroll
    for (int i = 0; i < 4; i++)
        #pragma unroll
        for (int j = 0; j < 8; j++) acc[i][j] = 0ull;

    float4 a4 = *(const float4*)(Ab + (size_t)lk * PP + lm);
    float4 b4 = *(const float4*)(Bb + lk * DD + lm);
    *(float4*)&As[lk][lm] = a4;
    *(float4*)&Bs[lk][lm] = b4;
    __syncthreads();

    const int KT = CC / 8;   // 256 k-tiles
    for (int kt = 0; kt < KT; kt++) {
        float4 a4n, b4n;
        if (kt + 1 < KT) {
            a4n = *(const float4*)(Ab + (size_t)((kt + 1) * 8 + lk) * PP + lm);
            b4n = *(const float4*)(Bb + ((kt + 1) * 8 + lk) * DD + lm);
        }
        #pragma unroll
        for (int k = 0; k < 8; k++) {
            const ull* arow = (const ull*)&As[k][crow];   // 4 row-pairs, LDS.64-native
            ull ap0 = arow[0], ap1 = arow[1], ap2 = arow[2], ap3 = arow[3];
            float4 bq0 = *(const float4*)&Bs[k][ccol];
            float4 bq1 = *(const float4*)&Bs[k][ccol + 4];
            float bs[8] = {bq0.x, bq0.y, bq0.z, bq0.w, bq1.x, bq1.y, bq1.z, bq1.w};
            #pragma unroll
            for (int j = 0; j < 8; j++) {
                ull bb = bcast2(bs[j]);
                ffma2(acc[0][j], ap0, bb);
                ffma2(acc[1][j], ap1, bb);
                ffma2(acc[2][j], ap2, bb);
                ffma2(acc[3][j], ap3, bb);
            }
        }
        __syncthreads();
        if (kt + 1 < KT) {
            *(float4*)&As[lk][lm] = a4n;
            *(float4*)&Bs[lk][lm] = b4n;
            __syncthreads();
        }
    }

    // ---- epilogue: store z, accumulate per-thread column sums/sumsq ----
    float cs[8], cq[8];
    #pragma unroll
    for (int j = 0; j < 8; j++) { cs[j] = 0.f; cq[j] = 0.f; }

    #pragma unroll
    for (int ip = 0; ip < 4; ip++) {
        float lo[8], hi[8];
        #pragma unroll
        for (int j = 0; j < 8; j++) {
            lo[j] = __uint_as_float((unsigned)(acc[ip][j] & 0xffffffffull));
            hi[j] = __uint_as_float((unsigned)(acc[ip][j] >> 32));
            cs[j] += lo[j] + hi[j];
            cq[j] += lo[j] * lo[j] + hi[j] * hi[j];
        }
        int r0 = m0 + crow + 2 * ip;
        float* z0 = g_z + (size_t)r0 * DD + n0 + ccol;
        float* z1 = z0 + DD;
        ((float4*)z0)[0] = make_float4(lo[0], lo[1], lo[2], lo[3]);
        ((float4*)z0)[1] = make_float4(lo[4], lo[5], lo[6], lo[7]);
        ((float4*)z1)[0] = make_float4(hi[0], hi[1], hi[2], hi[3]);
        ((float4*)z1)[1] = make_float4(hi[4], hi[5], hi[6], hi[7]);
    }

    // reduce column sums over the 16 ty-rows
    ((float4*)&red[ty][ccol])[0] = make_float4(cs[0], cs[1], cs[2], cs[3]);
    ((float4*)&red[ty][ccol])[1] = make_float4(cs[4], cs[5], cs[6], cs[7]);
    __syncthreads();
    if (tid < 128) {
        float s = 0.f;
        #pragma unroll
        for (int r = 0; r < 16; r++) s += red[r][tid];
        g_psum[by * DD + n0 + tid] = s;
    }
    __syncthreads();
    ((float4*)&red[ty][ccol])[0] = make_float4(cq[0], cq[1], cq[2], cq[3]);
    ((float4*)&red[ty][ccol])[1] = make_float4(cq[4], cq[5], cq[6], cq[7]);
    __syncthreads();
    if (tid < 128) {
        float s = 0.f;
        #pragma unroll
        for (int r = 0; r < 16; r++) s += red[r][tid];
        g_psq[by * DD + n0 + tid] = s;
    }
}

// =====================================================================
// Kernel 3: prep (grid = 3).
//   block 0: BN stats + gather/BN/ReLU/L2-normalize the 128 selected
//            rows -> g_nf; zero loss accumulators
//   block 1: mpos inverse norms -> g_mn[0..255]
//   block 2: mneg inverse norms -> g_mn[256..511]
// =====================================================================
__global__ void k_prep(const float* __restrict__ gamma,
                       const float* __restrict__ beta,
                       const float* __restrict__ mpos,
                       const float* __restrict__ mneg)
{
    const int blk = blockIdx.x;
    const int t = threadIdx.x;           // 256 threads
    const int warp = t >> 5, lane = t & 31;

    if (blk == 0) {
        __shared__ float s_mu[DD], s_istd[DD];
        if (t == 0) { g_acc[0] = 0.f; g_acc[1] = 0.f; g_cnt = 0.f; }

        float s = 0.f, q = 0.f;
        #pragma unroll 4
        for (int b2 = 0; b2 < 256; b2++) {
            s += g_psum[b2 * DD + t];
            q += g_psq[b2 * DD + t];
        }
        float mu  = s * (1.0f / 32768.0f);
        float var = q * (1.0f / 32768.0f) - mu * mu;
        s_mu[t]   = mu;
        s_istd[t] = 1.0f / sqrtf(var + 1e-5f);
        __syncthreads();

        for (int sr = warp; sr < 128; sr += 8) {
            int row = g_sel_idx[sr];
            const float* zr = g_z + (size_t)row * DD;
            float v[8]; float ss = 0.f;
            #pragma unroll
            for (int k = 0; k < 8; k++) {
                int d = lane + 32 * k;
                float x = (zr[d] - s_mu[d]) * s_istd[d] * gamma[d] + beta[d];
                x = fmaxf(x, 0.f);
                v[k] = x; ss += x * x;
            }
            #pragma unroll
            for (int o = 16; o; o >>= 1) ss += __shfl_xor_sync(0xffffffffu, ss, o);
            float inv = 1.0f / (sqrtf(ss) + 1e-12f);
            #pragma unroll
            for (int k = 0; k < 8; k++) g_nf[sr * DD + lane + 32 * k] = v[k] * inv;
        }
    } else {
        const float* m = (blk == 1) ? mpos : mneg;
        const int base = (blk - 1) * NMEM;
        for (int r = warp; r < NMEM; r += 8) {
            const float* mr = m + (size_t)r * DD;
            float ss = 0.f;
            #pragma unroll
            for (int k = 0; k < 8; k++) { float x = mr[lane + 32 * k]; ss += x * x; }
            #pragma unroll
            for (int o = 16; o; o >>= 1) ss += __shfl_xor_sync(0xffffffffu, ss, o);
            if (lane == 0) g_mn[base + r] = 1.0f / (sqrtf(ss) + 1e-12f);
        }
    }
}

// =====================================================================
// Kernel 4: InfoNCE, 64 blocks (task = loss*16 + anchor).
// loss: 0=l1(fg local) 1=l2(bg local) 2=g1(fg global) 3=g2(bg global)
// =====================================================================
__global__ void k_nce(const float* __restrict__ mpos,
                      const float* __restrict__ mneg)
{
    const int task = blockIdx.x;
    const int loss = task >> 4;
    const int a    = task & 15;
    const int qslot = (loss == 1 || loss == 3) ? (NS + a) : a;

    __shared__ float sq[DD];
    __shared__ float spe[8], sne[8];

    const int t = threadIdx.x;           // 256 threads
    const int warp = t >> 5, lane = t & 31;

    sq[t] = g_nf[qslot * DD + t];
    __syncthreads();

    float pe = 0.f, ne = 0.f;
    float ql[8];
    #pragma unroll
    for (int k = 0; k < 8; k++) ql[k] = sq[lane + 32 * k];

    if (loss < 2) {
        const int posbase = (loss == 0) ? 0 : NS;
        const int negbase = NS - posbase;
        for (int j = warp; j < NS; j += 8) {
            const float* p = g_nf + (size_t)(posbase + j) * DD;
            float d = 0.f;
            #pragma unroll
            for (int k = 0; k < 8; k++) d += ql[k] * p[lane + 32 * k];
            #pragma unroll
            for (int o = 16; o; o >>= 1) d += __shfl_xor_sync(0xffffffffu, d, o);
            pe += expf(d * 10.0f) * g_sel_valid[posbase + j];

            const float* n2 = g_nf + (size_t)(negbase + j) * DD;
            float dn = 0.f;
            #pragma unroll
            for (int k = 0; k < 8; k++) dn += ql[k] * n2[lane + 32 * k];
            #pragma unroll
            for (int o = 16; o; o >>= 1) dn += __shfl_xor_sync(0xffffffffu, dn, o);
            ne += expf(dn * 10.0f) * g_sel_valid[negbase + j];
        }
    } else {
        const float* pb = (loss == 2) ? mpos : mneg;
        const float* nb = (loss == 2) ? mneg : mpos;
        const int pno = (loss == 2) ? 0 : NMEM;
        for (int j = warp; j < NMEM; j += 8) {
            const float* p = pb + (size_t)j * DD;
            float d = 0.f;
            #pragma unroll
            for (int k = 0; k < 8; k++) d += ql[k] * p[lane + 32 * k];
            #pragma unroll
            for (int o = 16; o; o >>= 1) d += __shfl_xor_sync(0xffffffffu, d, o);
            pe += expf(d * g_mn[pno + j] * 10.0f);

            const float* n2 = nb + (size_t)j * DD;
            float dn = 0.f;
            #pragma unroll
            for (int k = 0; k < 8; k++) dn += ql[k] * n2[lane + 32 * k];
            #pragma unroll
            for (int o = 16; o; o >>= 1) dn += __shfl_xor_sync(0xffffffffu, dn, o);
            ne += expf(dn * g_mn[(pno ^ NMEM) + j] * 10.0f);
        }
    }

    if (lane == 0) { spe[warp] = pe; sne[warp] = ne; }
    __syncthreads();
    if (t == 0) {
        float P = 0.f, N = 0.f;
        #pragma unroll
        for (int w = 0; w < 8; w++) { P += spe[w]; N += sne[w]; }
        float qvalid = g_sel_valid[qslot];
        float lv = -logf(P / (P + N + 1e-8f) + 1e-8f);
        atomicAdd(&g_acc[loss >> 1], lv * qvalid);
        if (loss < 2) atomicAdd(&g_cnt, qvalid);
    }
}

// =====================================================================
// Kernel 5: scalar output
// =====================================================================
__global__ void k_out(float* __restrict__ out)
{
    float n = fmaxf(g_cnt, 1.0f);
    out[0] = g_acc[0] / n + g_acc[1] / n;
}

// =====================================================================
extern "C" void kernel_launch(void* const* d_in, const int* in_sizes, int n_in,
                              void* d_out, int out_size)
{
    const float* features = (const float*)d_in[0];
    const float* pred_ori = (const float*)d_in[1];
    const float* pred_aug = (const float*)d_in[2];
    const float* unc      = (const float*)d_in[3];
    const int*   labels   = (const int*)  d_in[4];
    const float* conv_w   = (const float*)d_in[5];
    // d_in[6] = conv_b: cancels exactly in BatchNorm -> unused
    const float* gamma    = (const float*)d_in[7];
    const float* beta     = (const float*)d_in[8];
    const float* mpos     = (const float*)d_in[9];
    const float* mneg     = (const float*)d_in[10];

    k_select<<<2, 1024>>>(pred_ori, pred_aug, unc, labels);
    dim3 ggrid(DD / 128, NPIX / 128);   // (2, 256)
    k_gemm<<<ggrid, 256>>>(features, conv_w);
    k_prep<<<3, 256>>>(gamma, beta, mpos, mneg);
    k_nce<<<64, 256>>>(mpos, mneg);
    k_out<<<1, 1>>>((float*)d_out);
}

// round 4
// speedup vs baseline: 3.0730x; 1.8648x over previous
#include <cuda_runtime.h>
#include <cuda_bf16.h>
#include <cstdint>
#include <math.h>

// Problem constants (fixed by setup_inputs)
#define NPIX 32768      // B*H*W = 8*64*64
#define PP   4096       // H*W
#define CC   2048       // channels (GEMM K)
#define DD   256        // projection dim (GEMM N)
#define NMEM 256        // memory bank rows
#define NS   64         // NUM_SAMPLES

// GEMM tiling (mma.sync path, sm_100-base compatible)
#define BK     32                  // K per stage
#define KT     (CC / BK)           // 64 k-iterations
#define STAGES 3
#define STGB   49152               // per stage: Ah8K + Al8K + Bh16K + Bl16K
#define SM_MMA (STAGES * STGB)     // 147456 dynamic smem

typedef unsigned long long ull;

// ---------------- device scratch (static: no allocations allowed) ----------
__device__ __align__(16) __nv_bfloat16 g_ah[(size_t)NPIX * CC];   // 134MB
__device__ __align__(16) __nv_bfloat16 g_al[(size_t)NPIX * CC];   // 134MB
__device__ __align__(16) __nv_bfloat16 g_bh[(size_t)DD * CC];     // 1MB
__device__ __align__(16) __nv_bfloat16 g_bl[(size_t)DD * CC];     // 1MB
__device__ float g_z[(size_t)NPIX * DD];        // projected features (pre-BN)
__device__ float g_psum[256 * DD];              // per-slab column sums
__device__ float g_psq[256 * DD];               // per-slab column sumsq
__device__ int   g_sel_idx[128];                // fg[0..63], bg[64..127]
__device__ float g_sel_valid[128];
__device__ float g_nf[128 * DD];                // normalized selected features
__device__ float g_mn[2 * NMEM];                // memory-bank inverse norms
__device__ float g_pe[64], g_ne[64];            // per-task exp sums

// ---------------- PTX helpers (all sm_100-base legal) ----------------
__device__ __forceinline__ uint32_t smem_u32(const void* p) {
    uint32_t a;
    asm("{ .reg .u64 t; cvta.to.shared.u64 t, %1; cvt.u32.u64 %0, t; }"
        : "=r"(a) : "l"(p));
    return a;
}

#define CP16(dst, src) \
    asm volatile("{ .reg .u64 p; cvta.to.global.u64 p, %1; " \
                 "cp.async.cg.shared.global [%0], [p], 16; }" \
                 :: "r"(dst), "l"(src))

#define CP_COMMIT() asm volatile("cp.async.commit_group;" ::: "memory")

#define LDSM4(r0, r1, r2, r3, addr) \
    asm volatile("ldmatrix.sync.aligned.m8n8.x4.shared.b16 {%0,%1,%2,%3}, [%4];" \
                 : "=r"(r0), "=r"(r1), "=r"(r2), "=r"(r3) : "r"(addr))

#define MMA_BF16(c, a, b0, b1) \
    asm volatile("mma.sync.aligned.m16n8k16.row.col.f32.bf16.bf16.f32 " \
                 "{%0,%1,%2,%3}, {%4,%5,%6,%7}, {%8,%9}, {%0,%1,%2,%3};" \
                 : "+f"((c)[0]), "+f"((c)[1]), "+f"((c)[2]), "+f"((c)[3]) \
                 : "r"((a)[0]), "r"((a)[1]), "r"((a)[2]), "r"((a)[3]), \
                   "r"(b0), "r"(b1))

// swizzled SMEM offset for row r (64B pitch), 16B-chunk c (0..3)
__device__ __forceinline__ uint32_t swz(int r, int c) {
    return (uint32_t)(r * 64 + 16 * (c ^ ((r >> 1) & 3)));
}

// =====================================================================
// Kernel 1: hard-sample mining. block 0 -> fg (label==1), block 1 -> bg.
// Iterative block-argmax (64 rounds) replicating jax.lax.top_k exactly.
// =====================================================================
__global__ void k_select(const float* __restrict__ pred_ori,
                         const float* __restrict__ pred_aug,
                         const float* __restrict__ unc,
                         const int*   __restrict__ labels)
{
    const int cls = blockIdx.x;          // 0: fg, 1: bg
    const int tid = threadIdx.x;         // 1024 threads
    const int want = cls ? 0 : 1;

    float sc[32];
    #pragma unroll
    for (int i = 0; i < 32; i++) {
        int n = tid + (i << 10);
        int b = n >> 12, p = n & 4095;
        const float* po = pred_ori + (size_t)b * 2 * PP + p;
        const float* pa = pred_aug + (size_t)b * 2 * PP + p;
        int io = po[PP] > po[0];
        int ia = pa[PP] > pa[0];
        float u = unc[n];
        bool ok = (io == ia) && (u > 0.5f) && (labels[n] == want);
        sc[i] = ok ? u : -1e9f;
    }

    float bv = -INFINITY; int bi = -1;
    #pragma unroll
    for (int i = 0; i < 32; i++) {
        int n = tid + (i << 10);
        if (sc[i] > bv || (sc[i] == bv && n < bi)) { bv = sc[i]; bi = n; }
    }

    __shared__ float wv[32];
    __shared__ int   wi[32];
    __shared__ int   winner;

    for (int it = 0; it < NS; it++) {
        float v = bv; int ix = bi;
        #pragma unroll
        for (int o = 16; o; o >>= 1) {
            float ov = __shfl_down_sync(0xffffffffu, v, o);
            int   oi = __shfl_down_sync(0xffffffffu, ix, o);
            if (ov > v || (ov == v && oi < ix)) { v = ov; ix = oi; }
        }
        if ((tid & 31) == 0) { wv[tid >> 5] = v; wi[tid >> 5] = ix; }
        __syncthreads();
        if (tid < 32) {
            v = wv[tid]; ix = wi[tid];
            #pragma unroll
            for (int o = 16; o; o >>= 1) {
                float ov = __shfl_down_sync(0xffffffffu, v, o);
                int   oi = __shfl_down_sync(0xffffffffu, ix, o);
                if (ov > v || (ov == v && oi < ix)) { v = ov; ix = oi; }
            }
            if (tid == 0) {
                winner = ix;
                g_sel_idx[cls * NS + it]   = ix;
                g_sel_valid[cls * NS + it] = (v > -5e8f) ? 1.0f : 0.0f;
            }
        }
        __syncthreads();
        int wn = winner;
        if ((wn & 1023) == tid) {
            sc[wn >> 10] = -INFINITY;
            bv = -INFINITY; bi = -1;
            #pragma unroll
            for (int i = 0; i < 32; i++) {
                int n = tid + (i << 10);
                if (sc[i] > bv || (sc[i] == bv && n < bi)) { bv = sc[i]; bi = n; }
            }
        }
        __syncthreads();
    }
}

// =====================================================================
// Kernel 2: convert + transpose to bf16 hi/lo operands.
//   blocks [0,512):      W[c,d]  -> Bh/Bl[n=d][k=c]
//   blocks [512,66048):  F[b,c,p]-> Ah/Al[m=b*4096+p][k=c]
// bf16x2 split: hi = bf16(f), lo = bf16(f - hi); combined ~2^-17 rel err.
// conv_b omitted: cancels exactly in BatchNorm.
// =====================================================================
__global__ void __launch_bounds__(256) k_conv(const float* __restrict__ F,
                                              const float* __restrict__ Wt)
{
    __shared__ float s[32][33];
    const int bid = blockIdx.x;
    const int tid = threadIdx.x;
    const int li = tid >> 5;      // 0..7
    const int lj = tid & 31;

    if (bid < 512) {
        const int d0 = (bid & 7) << 5, c0 = (bid >> 3) << 5;
        #pragma unroll
        for (int pp2 = 0; pp2 < 4; pp2++) {
            int i = li + pp2 * 8;
            s[i][lj] = Wt[(size_t)(c0 + i) * DD + d0 + lj];
        }
        __syncthreads();
        #pragma unroll
        for (int pp2 = 0; pp2 < 4; pp2++) {
            int r = li + pp2 * 8;           // d-local
            float f = s[lj][r];             // W[c0+lj][d0+r]
            __nv_bfloat16 h = __float2bfloat16(f);
            __nv_bfloat16 l = __float2bfloat16(f - __bfloat162float(h));
            g_bh[(size_t)(d0 + r) * CC + c0 + lj] = h;
            g_bl[(size_t)(d0 + r) * CC + c0 + lj] = l;
        }
    } else {
        const int t2 = bid - 512;
        const int tc = t2 & 63;             // c tile
        const int tp = t2 >> 6;             // m tile (32 rows, never crosses batch)
        const int c0 = tc << 5;
        const int m0 = tp << 5;
        const int b = m0 >> 12, p0 = m0 & 4095;
        const float* Fb = F + (size_t)b * CC * PP + (size_t)c0 * PP + p0;
        #pragma unroll
        for (int pp2 = 0; pp2 < 4; pp2++) {
            int i = li + pp2 * 8;
            s[i][lj] = Fb[(size_t)i * PP + lj];
        }
        __syncthreads();
        #pragma unroll
        for (int pp2 = 0; pp2 < 4; pp2++) {
            int r = li + pp2 * 8;           // m-local
            float f = s[lj][r];             // F[c0+lj][p0+r]
            __nv_bfloat16 h = __float2bfloat16(f);
            __nv_bfloat16 l = __float2bfloat16(f - __bfloat162float(h));
            g_ah[(size_t)(m0 + r) * CC + c0 + lj] = h;
            g_al[(size_t)(m0 + r) * CC + c0 + lj] = l;
        }
    }
}

// =====================================================================
// Kernel 3: bf16x3 GEMM via mma.sync (HMMA; works on sm_100 base).
//   Z[m,d] = Ah*Bh + Ah*Bl + Al*Bh, fp32 accumulators in registers.
// 256 CTAs: CTA tile M=128, N=256 (full), 3-stage cp.async pipeline.
// 8 warps (4m x 2n), warp tile 32x128, 128 acc regs/thread.
// Stage layout: [0,8K) Ah | [8K,16K) Al | [16K,32K) Bh | [32K,48K) Bl
// =====================================================================
__device__ __forceinline__ void mma_loads(uint32_t sA, int m0, int kb, int tid)
{
    #pragma unroll
    for (int i = 0; i < 4; i++) {
        int idx = tid + (i << 8);           // 0..1023
        int hl = idx >> 9, rem = idx & 511;
        int r = rem >> 2, c = rem & 3;
        const __nv_bfloat16* src =
            (hl ? g_al : g_ah) + (size_t)(m0 + r) * CC + kb + c * 8;
        CP16(sA + hl * 8192 + swz(r, c), src);
    }
    #pragma unroll
    for (int i = 0; i < 8; i++) {
        int idx = tid + (i << 8);           // 0..2047
        int hl = idx >> 10, rem = idx & 1023;
        int r = rem >> 2, c = rem & 3;
        const __nv_bfloat16* src =
            (hl ? g_bl : g_bh) + (size_t)r * CC + kb + c * 8;
        CP16(sA + 16384 + hl * 16384 + swz(r, c), src);
    }
}

__global__ void __launch_bounds__(256) k_mma()
{
    extern __shared__ char smem[];
    const uint32_t sb = smem_u32(smem);
    const int tid = threadIdx.x;
    const int wid = tid >> 5, lane = tid & 31;
    const int wm = wid & 3, wn = wid >> 2;
    const int m0 = blockIdx.x << 7;

    float acc[2][16][4];
    #pragma unroll
    for (int mi = 0; mi < 2; mi++)
        #pragma unroll
        for (int n8 = 0; n8 < 16; n8++)
            #pragma unroll
            for (int q = 0; q < 4; q++) acc[mi][n8][q] = 0.f;

    // prologue: preload STAGES-1 stages
    mma_loads(sb + 0 * STGB, m0, 0, tid);  CP_COMMIT();
    mma_loads(sb + 1 * STGB, m0, BK, tid); CP_COMMIT();

    for (int kt = 0; kt < KT; kt++) {
        asm volatile("cp.async.wait_group 1;" ::: "memory");
        __syncthreads();
        const int stage = kt % STAGES;
        const uint32_t sA = sb + stage * STGB;
        const uint32_t sB = sA + 16384;

        #pragma unroll
        for (int k16 = 0; k16 < 2; k16++) {
            const int kc = k16 * 2;
            uint32_t ah[2][4], al[2][4];
            #pragma unroll
            for (int mi = 0; mi < 2; mi++) {
                int r = wm * 32 + mi * 16 + (lane & 15);
                int cl = kc + (lane >> 4);
                uint32_t sw = swz(r, cl);
                LDSM4(ah[mi][0], ah[mi][1], ah[mi][2], ah[mi][3], sA + sw);
                LDSM4(al[mi][0], al[mi][1], al[mi][2], al[mi][3], sA + 8192 + sw);
            }
            #pragma unroll
            for (int g = 0; g < 8; g++) {
                int r = wn * 128 + g * 16 + (lane & 7) + ((lane >> 4) << 3);
                int cl = kc + ((lane >> 3) & 1);
                uint32_t sw = swz(r, cl);
                uint32_t bh[4], bl[4];
                LDSM4(bh[0], bh[1], bh[2], bh[3], sB + sw);
                LDSM4(bl[0], bl[1], bl[2], bl[3], sB + 16384 + sw);
                // pass order keeps acc dependency distance at 4
                #pragma unroll
                for (int mi = 0; mi < 2; mi++)
                    #pragma unroll
                    for (int s2 = 0; s2 < 2; s2++)
                        MMA_BF16(acc[mi][g * 2 + s2], ah[mi], bh[2 * s2], bh[2 * s2 + 1]);
                #pragma unroll
                for (int mi = 0; mi < 2; mi++)
                    #pragma unroll
                    for (int s2 = 0; s2 < 2; s2++)
                        MMA_BF16(acc[mi][g * 2 + s2], ah[mi], bl[2 * s2], bl[2 * s2 + 1]);
                #pragma unroll
                for (int mi = 0; mi < 2; mi++)
                    #pragma unroll
                    for (int s2 = 0; s2 < 2; s2++)
                        MMA_BF16(acc[mi][g * 2 + s2], al[mi], bh[2 * s2], bh[2 * s2 + 1]);
            }
        }

        const int nk = kt + STAGES - 1;
        if (nk < KT) {
            mma_loads(sb + (nk % STAGES) * STGB, m0, nk * BK, tid);
            CP_COMMIT();
        }
    }

    // epilogue: acc -> g_z (float2 stores; 32B-coalesced per lane-quad)
    #pragma unroll
    for (int mi = 0; mi < 2; mi++) {
        #pragma unroll
        for (int n8 = 0; n8 < 16; n8++) {
            int row = m0 + wm * 32 + mi * 16 + (lane >> 2);
            int col = wn * 128 + n8 * 8 + (lane & 3) * 2;
            *(float2*)(g_z + (size_t)row * DD + col) =
                make_float2(acc[mi][n8][0], acc[mi][n8][1]);
            *(float2*)(g_z + (size_t)(row + 8) * DD + col) =
                make_float2(acc[mi][n8][2], acc[mi][n8][3]);
        }
    }
}

// =====================================================================
// Kernel 4: per-column partial sums/sumsq over 128-row slabs of g_z
// =====================================================================
__global__ void k_colred()
{
    const int blk = blockIdx.x;   // 256 blocks
    const int t   = threadIdx.x;  // 256 threads (one column each)
    const float* base = g_z + (size_t)blk * 128 * DD + t;
    float s = 0.f, q = 0.f;
    #pragma unroll 4
    for (int r = 0; r < 128; r++) {
        float v = base[(size_t)r * DD];
        s += v;
        q += v * v;
    }
    g_psum[blk * DD + t] = s;
    g_psq [blk * DD + t] = q;
}

// =====================================================================
// Kernel 5: prep (grid = 3).
//   block 0: BN stats + gather/BN/ReLU/L2-normalize 128 rows -> g_nf;
//            zero per-task accumulators
//   block 1/2: memory-bank inverse norms
// =====================================================================
__global__ void k_prep(const float* __restrict__ gamma,
                       const float* __restrict__ beta,
                       const float* __restrict__ mpos,
                       const float* __restrict__ mneg)
{
    const int blk = blockIdx.x;
    const int t = threadIdx.x;           // 256 threads
    const int warp = t >> 5, lane = t & 31;

    if (blk == 0) {
        __shared__ float s_mu[DD], s_istd[DD];
        if (t < 64) { g_pe[t] = 0.f; g_ne[t] = 0.f; }

        float s = 0.f, q = 0.f;
        #pragma unroll 4
        for (int b2 = 0; b2 < 256; b2++) {
            s += g_psum[b2 * DD + t];
            q += g_psq[b2 * DD + t];
        }
        float mu  = s * (1.0f / 32768.0f);
        float var = q * (1.0f / 32768.0f) - mu * mu;
        s_mu[t]   = mu;
        s_istd[t] = 1.0f / sqrtf(var + 1e-5f);
        __syncthreads();

        for (int sr = warp; sr < 128; sr += 8) {
            int row = g_sel_idx[sr];
            const float* zr = g_z + (size_t)row * DD;
            float v[8]; float ss = 0.f;
            #pragma unroll
            for (int k = 0; k < 8; k++) {
                int d = lane + 32 * k;
                float x = (zr[d] - s_mu[d]) * s_istd[d] * gamma[d] + beta[d];
                x = fmaxf(x, 0.f);
                v[k] = x; ss += x * x;
            }
            #pragma unroll
            for (int o = 16; o; o >>= 1) ss += __shfl_xor_sync(0xffffffffu, ss, o);
            float inv = 1.0f / (sqrtf(ss) + 1e-12f);
            #pragma unroll
            for (int k = 0; k < 8; k++) g_nf[sr * DD + lane + 32 * k] = v[k] * inv;
        }
    } else {
        const float* m = (blk == 1) ? mpos : mneg;
        const int base = (blk - 1) * NMEM;
        for (int r = warp; r < NMEM; r += 8) {
            const float* mr = m + (size_t)r * DD;
            float ss = 0.f;
            #pragma unroll
            for (int k = 0; k < 8; k++) { float x = mr[lane + 32 * k]; ss += x * x; }
            #pragma unroll
            for (int o = 16; o; o >>= 1) ss += __shfl_xor_sync(0xffffffffu, ss, o);
            if (lane == 0) g_mn[base + r] = 1.0f / (sqrtf(ss) + 1e-12f);
        }
    }
}

// =====================================================================
// Kernel 6: InfoNCE partials, 256 blocks = 64 tasks x 4 j-chunks.
// loss: 0=l1(fg local) 1=l2(bg local) 2=g1(fg global) 3=g2(bg global)
// =====================================================================
__global__ void k_nce(const float* __restrict__ mpos,
                      const float* __restrict__ mneg)
{
    const int task  = blockIdx.x >> 2;
    const int chunk = blockIdx.x & 3;
    const int loss = task >> 4;
    const int a    = task & 15;
    const int qslot = (loss & 1) ? (NS + a) : a;

    __shared__ float sq[DD];
    __shared__ float spe[8], sne[8];

    const int t = threadIdx.x;           // 256 threads
    const int warp = t >> 5, lane = t & 31;

    sq[t] = g_nf[qslot * DD + t];
    __syncthreads();

    float pe = 0.f, ne = 0.f;
    float ql[8];
    #pragma unroll
    for (int k = 0; k < 8; k++) ql[k] = sq[lane + 32 * k];

    if (loss < 2) {
        const int posbase = (loss == 0) ? 0 : NS;
        const int negbase = NS - posbase;
        const int j0 = chunk * 16;
        for (int j = j0 + warp; j < j0 + 16; j += 8) {
            const float* p = g_nf + (size_t)(posbase + j) * DD;
            float d = 0.f;
            #pragma unroll
            for (int k = 0; k < 8; k++) d += ql[k] * p[lane + 32 * k];
            #pragma unroll
            for (int o = 16; o; o >>= 1) d += __shfl_xor_sync(0xffffffffu, d, o);
            pe += expf(d * 10.0f) * g_sel_valid[posbase + j];

            const float* n2 = g_nf + (size_t)(negbase + j) * DD;
            float dn = 0.f;
            #pragma unroll
            for (int k = 0; k < 8; k++) dn += ql[k] * n2[lane + 32 * k];
            #pragma unroll
            for (int o = 16; o; o >>= 1) dn += __shfl_xor_sync(0xffffffffu, dn, o);
            ne += expf(dn * 10.0f) * g_sel_valid[negbase + j];
        }
    } else {
        const float* pb = (loss == 2) ? mpos : mneg;
        const float* nb = (loss == 2) ? mneg : mpos;
        const int pno = (loss == 2) ? 0 : NMEM;
        const int j0 = chunk * 64;
        for (int j = j0 + warp; j < j0 + 64; j += 8) {
            const float* p = pb + (size_t)j * DD;
            float d = 0.f;
            #pragma unroll
            for (int k = 0; k < 8; k++) d += ql[k] * p[lane + 32 * k];
            #pragma unroll
            for (int o = 16; o; o >>= 1) d += __shfl_xor_sync(0xffffffffu, d, o);
            pe += expf(d * g_mn[pno + j] * 10.0f);

            const float* n2 = nb + (size_t)j * DD;
            float dn = 0.f;
            #pragma unroll
            for (int k = 0; k < 8; k++) dn += ql[k] * n2[lane + 32 * k];
            #pragma unroll
            for (int o = 16; o; o >>= 1) dn += __shfl_xor_sync(0xffffffffu, dn, o);
            ne += expf(dn * g_mn[(pno ^ NMEM) + j] * 10.0f);
        }
    }

    if (lane == 0) { spe[warp] = pe; sne[warp] = ne; }
    __syncthreads();
    if (t == 0) {
        float P = 0.f, N = 0.f;
        #pragma unroll
        for (int w = 0; w < 8; w++) { P += spe[w]; N += sne[w]; }
        atomicAdd(&g_pe[task], P);
        atomicAdd(&g_ne[task], N);
    }
}

// =====================================================================
// Kernel 7: final losses + scalar output (1 block, 64 threads)
// =====================================================================
__global__ void k_out(float* __restrict__ out)
{
    __shared__ float sw2[2];
    const int t = threadIdx.x;          // 64
    const int loss = t >> 4, a = t & 15;
    const int qslot = (loss & 1) ? (NS + a) : a;

    float P = g_pe[t], N = g_ne[t];
    float lv = -logf(P / (P + N + 1e-8f) + 1e-8f) * g_sel_valid[qslot];

    #pragma unroll
    for (int o = 16; o; o >>= 1) lv += __shfl_down_sync(0xffffffffu, lv, o);
    if ((t & 31) == 0) sw2[t >> 5] = lv;
    __syncthreads();
    if (t == 0) {
        float total = sw2[0] + sw2[1];
        float n = 0.f;
        #pragma unroll
        for (int i = 0; i < 16; i++) n += g_sel_valid[i] + g_sel_valid[NS + i];
        n = fmaxf(n, 1.0f);
        out[0] = total / n;
    }
}

// =====================================================================
extern "C" void kernel_launch(void* const* d_in, const int* in_sizes, int n_in,
                              void* d_out, int out_size)
{
    const float* features = (const float*)d_in[0];
    const float* pred_ori = (const float*)d_in[1];
    const float* pred_aug = (const float*)d_in[2];
    const float* unc      = (const float*)d_in[3];
    const int*   labels   = (const int*)  d_in[4];
    const float* conv_w   = (const float*)d_in[5];
    // d_in[6] = conv_b: cancels exactly in BatchNorm -> unused
    const float* gamma    = (const float*)d_in[7];
    const float* beta     = (const float*)d_in[8];
    const float* mpos     = (const float*)d_in[9];
    const float* mneg     = (const float*)d_in[10];

    static int smem_set = 0;
    if (!smem_set) {
        cudaFuncSetAttribute(k_mma, cudaFuncAttributeMaxDynamicSharedMemorySize, SM_MMA);
        smem_set = 1;
    }

    k_select<<<2, 1024>>>(pred_ori, pred_aug, unc, labels);
    k_conv<<<512 + 65536, 256>>>(features, conv_w);
    k_mma<<<256, 256, SM_MMA>>>();
    k_colred<<<256, 256>>>();
    k_prep<<<3, 256>>>(gamma, beta, mpos, mneg);
    k_nce<<<256, 256>>>(mpos, mneg);
    k_out<<<1, 64>>>((float*)d_out);
}